// round 13
// baseline (speedup 1.0000x reference)
#include <cuda_runtime.h>
#include <cuda_bf16.h>
#include <cstdint>

// ---------------------------------------------------------------------------
// KITRO via warp-level bf16 mma.sync (HMMA.16816).
// Persistent single-wave 4-stage cp.async GEMM, 512-thread CTAs, 128x256 tiles.
// B=8192, J=25, FDIM=512, HDIM=1024.  M = B*J = 204800 rows (1600 m-tiles).
//
// prep : features -> bf16 (g_Fbf), weights transposed to [n][k] bf16, depth=0
// GEMM1: H1[204800,1024](bf16) = relu(Fbf @ dW1 + db1)
// fproj: g_fproj[204800,32](f32) = Fbf @ cW1[4:] + cb1
// GEMM2 (fused GEMV): depth[m] += sum_n relu(H1@dW2+db2)[m,n] * dW3[n]
// bones: 4 batches per block, 3 refinement iterations in smem.
// ---------------------------------------------------------------------------

#define MROWS 204800
#define NTILESM 1600
#define K1    512
#define K2    1024
#define SPAD  72                      // smem row stride in bf16 (64 + 8 pad)
#define ASTG  18432                   // 128*72*2 bytes
#define BSTG  36864                   // 256*72*2 bytes
#define STG   (ASTG + BSTG)           // 55296
#define GEMM_SMEM (4 * STG)           // 221184 bytes dynamic

__device__ __nv_bfloat16 g_Fbf[(size_t)MROWS * K1];    // 210 MB
__device__ __nv_bfloat16 g_BT1[1024 * K1];             // [n][k]
__device__ __nv_bfloat16 g_BTf[32 * K1];               // [n][k] fproj weights
__device__ __nv_bfloat16 g_BT2[512 * K2];              // [n][k]
__device__ __nv_bfloat16 g_H1[(size_t)MROWS * 1024];   // 420 MB
__device__ float         g_fproj[(size_t)MROWS * 32];  // 26 MB
__device__ float         g_depth[MROWS];

__constant__ int c_par[16] = {0, 0, 0, 0, 0, 0, 5, 7, 6, 8, 5, 6, 11, 13, 12, 14};
__constant__ int c_chi[16] = {1, 2, 3, 4, 5, 6, 7, 9, 8, 10, 11, 12, 13, 15, 14, 16};

// ------------------------------ helpers ------------------------------------
__device__ __forceinline__ uint32_t s2u(const void* p) {
    uint32_t a;
    asm("{ .reg .u64 t; cvta.to.shared.u64 t, %1; cvt.u32.u64 %0, t; }"
        : "=r"(a) : "l"(p));
    return a;
}
__device__ __forceinline__ void ldmat_x4(uint32_t* r, uint32_t addr) {
    asm volatile("ldmatrix.sync.aligned.m8n8.x4.shared.b16 {%0,%1,%2,%3}, [%4];"
                 : "=r"(r[0]), "=r"(r[1]), "=r"(r[2]), "=r"(r[3]) : "r"(addr));
}
__device__ __forceinline__ void ldmat_x2(uint32_t* r, uint32_t addr) {
    asm volatile("ldmatrix.sync.aligned.m8n8.x2.shared.b16 {%0,%1}, [%2];"
                 : "=r"(r[0]), "=r"(r[1]) : "r"(addr));
}
__device__ __forceinline__ void mma16816(float* c, const uint32_t* a, const uint32_t* b) {
    asm volatile(
        "mma.sync.aligned.m16n8k16.row.col.f32.bf16.bf16.f32 "
        "{%0,%1,%2,%3}, {%4,%5,%6,%7}, {%8,%9}, {%0,%1,%2,%3};"
        : "+f"(c[0]), "+f"(c[1]), "+f"(c[2]), "+f"(c[3])
        : "r"(a[0]), "r"(a[1]), "r"(a[2]), "r"(a[3]), "r"(b[0]), "r"(b[1]));
}
__device__ __forceinline__ void cpa16(uint32_t dst, const void* src) {
    asm volatile("cp.async.cg.shared.global [%0], [%1], 16;" :: "r"(dst), "l"(src));
}
__device__ __forceinline__ void cp_commit() {
    asm volatile("cp.async.commit_group;" ::: "memory");
}
template <int N> __device__ __forceinline__ void cp_wait() {
    asm volatile("cp.async.wait_group %0;" :: "n"(N) : "memory");
}

// ------------------------------- prep --------------------------------------
__global__ void prep_kernel(const float* __restrict__ features,
                            const float* __restrict__ dW1,
                            const float* __restrict__ dW2,
                            const float* __restrict__ cW1) {
    const int gid = blockIdx.x * blockDim.x + threadIdx.x;
    const int stride = gridDim.x * blockDim.x;
    for (int i = gid; i < MROWS * K1 / 8; i += stride) {
        const float4 f0 = ((const float4*)features)[i * 2];
        const float4 f1 = ((const float4*)features)[i * 2 + 1];
        __nv_bfloat162 p0 = __floats2bfloat162_rn(f0.x, f0.y);
        __nv_bfloat162 p1 = __floats2bfloat162_rn(f0.z, f0.w);
        __nv_bfloat162 p2 = __floats2bfloat162_rn(f1.x, f1.y);
        __nv_bfloat162 p3 = __floats2bfloat162_rn(f1.z, f1.w);
        uint4 pk = make_uint4(*(uint32_t*)&p0, *(uint32_t*)&p1,
                              *(uint32_t*)&p2, *(uint32_t*)&p3);
        ((uint4*)g_Fbf)[i] = pk;
    }
    for (int i = gid; i < 1024 * K1; i += stride) {
        int n = i >> 9, k = i & 511;
        g_BT1[i] = __float2bfloat16(dW1[k * 1024 + n]);
    }
    for (int i = gid; i < 32 * K1; i += stride) {
        int n = i >> 9, k = i & 511;
        g_BTf[i] = __float2bfloat16(cW1[(4 + k) * 32 + n]);
    }
    for (int i = gid; i < 512 * K2; i += stride) {
        int n = i >> 10, k = i & 1023;
        g_BT2[i] = __float2bfloat16(dW2[k * 512 + n]);
    }
    for (int i = gid; i < MROWS; i += stride) g_depth[i] = 0.f;
}

// ----------------- persistent 4-stage mma.sync GEMM ------------------------
// 512 threads, 16 warps (2 m x 8 n), warp tile 64x32, block tile 128x256.
// K chunks of 64; NCH = K/64 (compile-time). One CTA per SM, persistent over
// m-tiles strided by gridDim.y.
// MODE 0: C(bf16) = relu(A@B^T + bias)
// MODE 1: atomicAdd(g_depth[row], sum_n relu(A@B^T + bias)[n] * w3[n])
template <int MODE, int NCH>
__global__ void __launch_bounds__(512, 1)
gemm_pers(const __nv_bfloat16* __restrict__ A, int lda,
          const __nv_bfloat16* __restrict__ BT, int ldb,
          const float* __restrict__ bias,
          __nv_bfloat16* __restrict__ C, int ldc,
          const float* __restrict__ w3)
{
    extern __shared__ __align__(16) char smem[];
    __shared__ float sAux[256];
    __shared__ float sW3[256];

    const int tid  = threadIdx.x;
    const int wid  = tid >> 5, lane = tid & 31;
    const int wm   = wid >> 3;          // 0..1 -> 64-row slab
    const int wn   = wid & 7;           // 0..7 -> 32-col slab
    const int n0   = blockIdx.x * 256;
    const int by   = blockIdx.y, gy = gridDim.y;

    if (tid < 256) sAux[tid] = bias[n0 + tid];
    if (MODE == 1 && tid < 256) sW3[tid] = w3[n0 + tid];

    const uint32_t smbase = s2u(smem);
    const uint32_t aAoff = ((wm * 64 + (lane & 15)) * SPAD + (lane >> 4) * 8) << 1;
    const uint32_t aBoff = ASTG + ((((wn * 32 + (lane & 7)) * SPAD) + ((lane >> 3) & 1) * 8) << 1);

    const int srow = tid >> 3, soc = tid & 7;   // staging coords

    const int ntiles = (NTILESM - by + gy - 1) / gy;
    const int T = ntiles * NCH;

    // issue loads for global chunk t into stage t&3
    auto issue = [&](int t) {
        const int til = t / NCH, ch = t - til * NCH;
        const size_t m0i = (size_t)(by + til * gy) * 128;
        const int k0 = ch << 6;
        const __nv_bfloat16* Ap = A + m0i * lda + k0;
        const __nv_bfloat16* Bp = BT + (size_t)n0 * ldb + k0;
        const uint32_t sa = smbase + (uint32_t)(t & 3) * STG;
        cpa16(sa + (((srow)      * SPAD + soc * 8) << 1), Ap + (size_t)srow * lda + soc * 8);
        cpa16(sa + (((srow + 64) * SPAD + soc * 8) << 1), Ap + (size_t)(srow + 64) * lda + soc * 8);
#pragma unroll
        for (int i = 0; i < 4; i++) {
            int row = srow + i * 64;
            cpa16(sa + ASTG + ((row * SPAD + soc * 8) << 1), Bp + (size_t)row * ldb + soc * 8);
        }
    };

    float acc[4][4][4];
#pragma unroll
    for (int i = 0; i < 4; i++)
#pragma unroll
        for (int j = 0; j < 4; j++)
#pragma unroll
            for (int k = 0; k < 4; k++) acc[i][j][k] = 0.f;

    // prologue: 3 chunks ahead
#pragma unroll
    for (int t = 0; t < 3; t++) {
        if (t < T) issue(t);
        cp_commit();
    }

    for (int t = 0; t < T; t++) {
        cp_wait<2>();          // chunk t's data complete (this thread)
        __syncthreads();       // publish + all warps done with stage (t+3)&3
        if (t + 3 < T) issue(t + 3);
        cp_commit();

        const uint32_t boff = smbase + (uint32_t)(t & 3) * STG;
#pragma unroll
        for (int ks = 0; ks < 4; ks++) {
            uint32_t af[4][4], bf[4][2];
#pragma unroll
            for (int mt = 0; mt < 4; mt++)
                ldmat_x4(af[mt], boff + aAoff + ((mt * 16 * SPAD + ks * 16) << 1));
#pragma unroll
            for (int nt = 0; nt < 4; nt++)
                ldmat_x2(bf[nt], boff + aBoff + ((nt * 8 * SPAD + ks * 16) << 1));
#pragma unroll
            for (int mt = 0; mt < 4; mt++)
#pragma unroll
                for (int nt = 0; nt < 4; nt++)
                    mma16816(acc[mt][nt], af[mt], bf[nt]);
        }

        if ((t % NCH) == NCH - 1) {
            // -------- per-tile epilogue --------
            const int til = t / NCH;
            const int m0 = (by + til * gy) * 128;
            const int rbase = m0 + wm * 64 + (lane >> 2);
            const int clocal0 = wn * 32 + (lane & 3) * 2;
            if (MODE == 0) {
#pragma unroll
                for (int mt = 0; mt < 4; mt++) {
                    int r0 = rbase + mt * 16;
#pragma unroll
                    for (int nt = 0; nt < 4; nt++) {
                        int cl = clocal0 + nt * 8;
                        float b0 = sAux[cl], b1 = sAux[cl + 1];
                        float v0 = fmaxf(acc[mt][nt][0] + b0, 0.f);
                        float v1 = fmaxf(acc[mt][nt][1] + b1, 0.f);
                        float v2 = fmaxf(acc[mt][nt][2] + b0, 0.f);
                        float v3 = fmaxf(acc[mt][nt][3] + b1, 0.f);
                        *(__nv_bfloat162*)(C + (size_t)r0 * ldc + n0 + cl) =
                            __floats2bfloat162_rn(v0, v1);
                        *(__nv_bfloat162*)(C + (size_t)(r0 + 8) * ldc + n0 + cl) =
                            __floats2bfloat162_rn(v2, v3);
                    }
                }
            } else {
#pragma unroll
                for (int mt = 0; mt < 4; mt++) {
                    float s0 = 0.f, s1 = 0.f;
#pragma unroll
                    for (int nt = 0; nt < 4; nt++) {
                        int cl = clocal0 + nt * 8;
                        float b0 = sAux[cl], b1 = sAux[cl + 1];
                        float w0 = sW3[cl],  w1 = sW3[cl + 1];
                        s0 += fmaxf(acc[mt][nt][0] + b0, 0.f) * w0
                            + fmaxf(acc[mt][nt][1] + b1, 0.f) * w1;
                        s1 += fmaxf(acc[mt][nt][2] + b0, 0.f) * w0
                            + fmaxf(acc[mt][nt][3] + b1, 0.f) * w1;
                    }
                    s0 += __shfl_xor_sync(0xffffffffu, s0, 1);
                    s0 += __shfl_xor_sync(0xffffffffu, s0, 2);
                    s1 += __shfl_xor_sync(0xffffffffu, s1, 1);
                    s1 += __shfl_xor_sync(0xffffffffu, s1, 2);
                    if ((lane & 3) == 0) {
                        int r0 = rbase + mt * 16;
                        atomicAdd(&g_depth[r0], s0);
                        atomicAdd(&g_depth[r0 + 8], s1);
                    }
                }
            }
#pragma unroll
            for (int i = 0; i < 4; i++)
#pragma unroll
                for (int j = 0; j < 4; j++)
#pragma unroll
                    for (int k = 0; k < 4; k++) acc[i][j][k] = 0.f;
        }
    }
}

// ------------------------------- fproj -------------------------------------
// g_fproj[204800,32] = Fbf @ BTf^T + cb1.  Block 128 rows, warp tile 16x32.
__global__ void __launch_bounds__(256, 2)
fproj_kernel(const __nv_bfloat16* __restrict__ Fbf,
             const __nv_bfloat16* __restrict__ BTf,
             const float* __restrict__ cb1)
{
    __shared__ __align__(16) __nv_bfloat16 sA[128 * SPAD];   // 18 KB
    __shared__ __align__(16) __nv_bfloat16 sB[32 * SPAD];    // 4.5 KB
    __shared__ float sCb[32];

    const int tid = threadIdx.x;
    const int wid = tid >> 5, lane = tid & 31;
    const int m0 = blockIdx.x * 128;

    if (tid < 32) sCb[tid] = cb1[tid];

    const uint32_t aA = s2u(sA), aB = s2u(sB);
    const uint32_t aAf = aA + (((wid * 16 + (lane & 15)) * SPAD + (lane >> 4) * 8) << 1);
    const uint32_t aBf = aB + (((lane & 7) * SPAD + ((lane >> 3) & 1) * 8) << 1);

    float acc[4][4];
#pragma unroll
    for (int i = 0; i < 4; i++)
#pragma unroll
        for (int j = 0; j < 4; j++) acc[i][j] = 0.f;

    for (int ch = 0; ch < 8; ch++) {
        const int k0 = ch << 6;
        __syncthreads();
#pragma unroll
        for (int i = 0; i < 4; i++) {
            int q = i * 256 + tid, row = q >> 3, oc = q & 7;
            *(uint4*)&sA[row * SPAD + oc * 8] =
                *(const uint4*)(Fbf + (size_t)(m0 + row) * K1 + k0 + oc * 8);
        }
        {
            int row = tid >> 3, oc = tid & 7;
            *(uint4*)&sB[row * SPAD + oc * 8] =
                *(const uint4*)(BTf + (size_t)row * K1 + k0 + oc * 8);
        }
        __syncthreads();
#pragma unroll
        for (int ks = 0; ks < 4; ks++) {
            uint32_t af[4];
            ldmat_x4(af, aAf + (ks * 16 << 1));
#pragma unroll
            for (int nt = 0; nt < 4; nt++) {
                uint32_t bf[2];
                ldmat_x2(bf, aBf + ((nt * 8 * SPAD + ks * 16) << 1));
                mma16816(acc[nt], af, bf);
            }
        }
    }

    const int r = m0 + wid * 16 + (lane >> 2);
    const int c = (lane & 3) * 2;
#pragma unroll
    for (int nt = 0; nt < 4; nt++) {
        int col = c + nt * 8;
        float b0 = sCb[col], b1 = sCb[col + 1];
        *(float2*)&g_fproj[(size_t)r * 32 + col] =
            make_float2(acc[nt][0] + b0, acc[nt][1] + b1);
        *(float2*)&g_fproj[(size_t)(r + 8) * 32 + col] =
            make_float2(acc[nt][2] + b0, acc[nt][3] + b1);
    }
}

// ------------------------------- bones -------------------------------------
// 4 batches per block (64 threads each), 3 refinement iterations in smem.
__global__ void __launch_bounds__(256)
bones_kernel(const float* __restrict__ poses2d, const float* __restrict__ conf,
             const float* __restrict__ cW1, const float* __restrict__ cW2,
             const float* __restrict__ cb2, const float* __restrict__ cW3,
             const float* __restrict__ cb3, const float* __restrict__ db3,
             float* __restrict__ out)
{
    __shared__ float w1[4][32];
    __shared__ float w2[32][64];
    __shared__ float b2[64];
    __shared__ float w3s[64][3];
    __shared__ float b3[3];
    __shared__ float p3[4][75];
    __shared__ float cf[4][25];
    __shared__ float basef[4][16][32];
    __shared__ float dir4[4][16][4];
    __shared__ float g1[4][16][32];
    __shared__ float g2[4][16][64];
    __shared__ float bfm[4][16][3];
    __shared__ float upd[4][3];

    const int tid = threadIdx.x;
    const int u = tid >> 6, t = tid & 63;
    const size_t rowbase = ((size_t)blockIdx.x * 4 + u) * 25;

    if (tid < 128) ((float*)w1)[tid] = cW1[tid];
    for (int idx = tid; idx < 2048; idx += 256) ((float*)w2)[idx] = cW2[idx];
    if (tid < 64)  b2[tid] = cb2[tid];
    if (tid < 192) ((float*)w3s)[tid] = cW3[tid];
    if (tid < 3)   b3[tid] = cb3[tid];

    const float db3v = db3[0];
    if (t < 25) cf[u][t] = conf[rowbase + t];
    for (int idx = t; idx < 75; idx += 64) {
        int j = idx / 3, c = idx - j * 3;
        p3[u][idx] = (c < 2) ? poses2d[(rowbase + j) * 2 + c]
                             : (g_depth[rowbase + j] + db3v);
    }
    for (int idx = t; idx < 512; idx += 64) {
        int bone = idx >> 5, n = idx & 31;
        float fp = g_fproj[(rowbase + c_par[bone]) * 32 + n];
        float fc = g_fproj[(rowbase + c_chi[bone]) * 32 + n];
        basef[u][bone][n] = 0.5f * (fp + fc);
    }
    __syncthreads();

    for (int it = 0; it < 3; it++) {
        if (t < 16) {
            int p = c_par[t], c = c_chi[t];
            float vx = p3[u][c * 3 + 0] - p3[u][p * 3 + 0];
            float vy = p3[u][c * 3 + 1] - p3[u][p * 3 + 1];
            float vz = p3[u][c * 3 + 2] - p3[u][p * 3 + 2];
            float len = sqrtf(vx * vx + vy * vy + vz * vz);
            float inv = 1.f / (len + 1e-8f);
            dir4[u][t][0] = vx * inv;
            dir4[u][t][1] = vy * inv;
            dir4[u][t][2] = vz * inv;
            dir4[u][t][3] = len;
        }
        __syncthreads();
        for (int idx = t; idx < 512; idx += 64) {
            int bone = idx >> 5, n = idx & 31;
            float v = basef[u][bone][n]
                    + dir4[u][bone][0] * w1[0][n] + dir4[u][bone][1] * w1[1][n]
                    + dir4[u][bone][2] * w1[2][n] + dir4[u][bone][3] * w1[3][n];
            g1[u][bone][n] = fmaxf(v, 0.f);
        }
        __syncthreads();
        for (int idx = t; idx < 1024; idx += 64) {
            int bone = idx >> 6, n = idx & 63;
            float s = b2[n];
#pragma unroll
            for (int i = 0; i < 32; i++) s += g1[u][bone][i] * w2[i][n];
            g2[u][bone][n] = fmaxf(s, 0.f);
        }
        __syncthreads();
        if (t < 48) {
            int bone = t / 3, c = t - bone * 3;
            float s = b3[c];
#pragma unroll
            for (int i = 0; i < 64; i++) s += g2[u][bone][i] * w3s[i][c];
            bfm[u][bone][c] = s;
        }
        __syncthreads();
        if (t < 3) {
            float s = 0.f;
#pragma unroll
            for (int bone = 0; bone < 16; bone++) s += bfm[u][bone][t];
            upd[u][t] = 0.1f * (s * (1.f / 16.f));
        }
        __syncthreads();
        for (int idx = t; idx < 75; idx += 64) {
            int j = idx / 3, c = idx - j * 3;
            p3[u][idx] = (p3[u][idx] + upd[u][c]) * cf[u][j];
        }
        __syncthreads();
    }

    for (int idx = t; idx < 75; idx += 64) out[rowbase * 3 + idx] = p3[u][idx];
}

// ------------------------------ launcher -----------------------------------
extern "C" void kernel_launch(void* const* d_in, const int* in_sizes, int n_in,
                              void* d_out, int out_size) {
    (void)in_sizes; (void)n_in; (void)out_size;
    const float* poses2d  = (const float*)d_in[0];
    const float* features = (const float*)d_in[1];
    const float* conf     = (const float*)d_in[2];
    const float* dW1 = (const float*)d_in[3];
    const float* db1 = (const float*)d_in[4];
    const float* dW2 = (const float*)d_in[5];
    const float* db2 = (const float*)d_in[6];
    const float* dW3 = (const float*)d_in[7];
    const float* db3 = (const float*)d_in[8];
    const float* cW1 = (const float*)d_in[9];
    const float* cb1 = (const float*)d_in[10];
    const float* cW2 = (const float*)d_in[11];
    const float* cb2 = (const float*)d_in[12];
    const float* cW3 = (const float*)d_in[13];
    const float* cb3 = (const float*)d_in[14];
    float* out = (float*)d_out;

    __nv_bfloat16 *pFbf, *pBT1, *pBTf, *pBT2, *pH1;
    cudaGetSymbolAddress((void**)&pFbf, g_Fbf);
    cudaGetSymbolAddress((void**)&pBT1, g_BT1);
    cudaGetSymbolAddress((void**)&pBTf, g_BTf);
    cudaGetSymbolAddress((void**)&pBT2, g_BT2);
    cudaGetSymbolAddress((void**)&pH1, g_H1);

    cudaFuncSetAttribute(gemm_pers<0, 8>,  cudaFuncAttributeMaxDynamicSharedMemorySize, GEMM_SMEM);
    cudaFuncSetAttribute(gemm_pers<1, 16>, cudaFuncAttributeMaxDynamicSharedMemorySize, GEMM_SMEM);

    // 1) convert features + transpose weights + zero depth
    prep_kernel<<<8192, 256>>>(features, dW1, dW2, cW1);

    // 2) GEMM1: H1 = relu(Fbf @ dW1 + db1)  (bf16 out, N=1024) — 4x37 = 148 CTAs
    gemm_pers<0, 8><<<dim3(4, 37), 512, GEMM_SMEM>>>(
        pFbf, K1, pBT1, K1, db1, pH1, 1024, nullptr);

    // 3) fproj: g_fproj = Fbf @ cW1[4:] + cb1  (f32, N=32)
    fproj_kernel<<<NTILESM, 256>>>(pFbf, pBTf, cb1);

    // 4) GEMM2 fused GEMV: depth += relu(H1@dW2+db2) @ dW3 — 2x74 = 148 CTAs
    gemm_pers<1, 16><<<dim3(2, 74), 512, GEMM_SMEM>>>(
        pH1, K2, pBT2, K2, db2, nullptr, 0, dW3);

    // 5) skeletal refinement (adds db3 to depth)
    bones_kernel<<<2048, 256>>>(poses2d, conf, cW1, cW2, cb2, cW3, cb3, db3, out);
}

// round 14
// speedup vs baseline: 1.0341x; 1.0341x over previous
#include <cuda_runtime.h>
#include <cuda_bf16.h>
#include <cstdint>

// ---------------------------------------------------------------------------
// KITRO via warp-level bf16 mma.sync (HMMA.16816), 3-stage cp.async pipeline,
// 128x128 tiles, 256 threads, 2 CTAs/SM (cross-CTA bubble hiding).
// B=8192, J=25, FDIM=512, HDIM=1024.  M = B*J = 204800 rows.
//
// prep : features -> bf16 (g_Fbf), weights transposed to [n][k] bf16, depth=0
// GEMM1: H1[204800,1024](bf16) = relu(Fbf @ dW1 + db1)
// fproj: g_fproj[204800,32](f32) = Fbf @ cW1[4:] + cb1
// GEMM2 (fused GEMV): depth[m] += sum_n relu(H1@dW2+db2)[m,n] * dW3[n]
// bones: 4 batches per block, 3 refinement iterations in smem.
// ---------------------------------------------------------------------------

#define MROWS 204800
#define K1    512
#define K2    1024
#define SPAD  72                      // smem row stride in bf16 (64 + 8 pad)
#define BUFELEM (128 * SPAD)          // 9216 bf16 per A or B stage
#define BUFBYTES (BUFELEM * 2)        // 18432
#define STG   (2 * BUFBYTES)          // 36864 per stage (A+B)
#define GEMM_SMEM (3 * STG)           // 110592 bytes dynamic

__device__ __nv_bfloat16 g_Fbf[(size_t)MROWS * K1];    // 210 MB
__device__ __nv_bfloat16 g_BT1[1024 * K1];             // [n][k]
__device__ __nv_bfloat16 g_BTf[32 * K1];               // [n][k] fproj weights
__device__ __nv_bfloat16 g_BT2[512 * K2];              // [n][k]
__device__ __nv_bfloat16 g_H1[(size_t)MROWS * 1024];   // 420 MB
__device__ float         g_fproj[(size_t)MROWS * 32];  // 26 MB
__device__ float         g_depth[MROWS];

__constant__ int c_par[16] = {0, 0, 0, 0, 0, 0, 5, 7, 6, 8, 5, 6, 11, 13, 12, 14};
__constant__ int c_chi[16] = {1, 2, 3, 4, 5, 6, 7, 9, 8, 10, 11, 12, 13, 15, 14, 16};

// ------------------------------ helpers ------------------------------------
__device__ __forceinline__ uint32_t s2u(const void* p) {
    uint32_t a;
    asm("{ .reg .u64 t; cvta.to.shared.u64 t, %1; cvt.u32.u64 %0, t; }"
        : "=r"(a) : "l"(p));
    return a;
}
__device__ __forceinline__ void ldmat_x4(uint32_t* r, uint32_t addr) {
    asm volatile("ldmatrix.sync.aligned.m8n8.x4.shared.b16 {%0,%1,%2,%3}, [%4];"
                 : "=r"(r[0]), "=r"(r[1]), "=r"(r[2]), "=r"(r[3]) : "r"(addr));
}
__device__ __forceinline__ void ldmat_x2(uint32_t* r, uint32_t addr) {
    asm volatile("ldmatrix.sync.aligned.m8n8.x2.shared.b16 {%0,%1}, [%2];"
                 : "=r"(r[0]), "=r"(r[1]) : "r"(addr));
}
__device__ __forceinline__ void mma16816(float* c, const uint32_t* a, const uint32_t* b) {
    asm volatile(
        "mma.sync.aligned.m16n8k16.row.col.f32.bf16.bf16.f32 "
        "{%0,%1,%2,%3}, {%4,%5,%6,%7}, {%8,%9}, {%0,%1,%2,%3};"
        : "+f"(c[0]), "+f"(c[1]), "+f"(c[2]), "+f"(c[3])
        : "r"(a[0]), "r"(a[1]), "r"(a[2]), "r"(a[3]), "r"(b[0]), "r"(b[1]));
}
__device__ __forceinline__ void cpa16(uint32_t dst, const void* src) {
    asm volatile("cp.async.cg.shared.global [%0], [%1], 16;" :: "r"(dst), "l"(src));
}
__device__ __forceinline__ void cp_commit() {
    asm volatile("cp.async.commit_group;" ::: "memory");
}
template <int N> __device__ __forceinline__ void cp_wait() {
    asm volatile("cp.async.wait_group %0;" :: "n"(N) : "memory");
}

// ------------------------------- prep --------------------------------------
__global__ void prep_kernel(const float* __restrict__ features,
                            const float* __restrict__ dW1,
                            const float* __restrict__ dW2,
                            const float* __restrict__ cW1) {
    const int gid = blockIdx.x * blockDim.x + threadIdx.x;
    const int stride = gridDim.x * blockDim.x;
    for (int i = gid; i < MROWS * K1 / 8; i += stride) {
        const float4 f0 = ((const float4*)features)[i * 2];
        const float4 f1 = ((const float4*)features)[i * 2 + 1];
        __nv_bfloat162 p0 = __floats2bfloat162_rn(f0.x, f0.y);
        __nv_bfloat162 p1 = __floats2bfloat162_rn(f0.z, f0.w);
        __nv_bfloat162 p2 = __floats2bfloat162_rn(f1.x, f1.y);
        __nv_bfloat162 p3 = __floats2bfloat162_rn(f1.z, f1.w);
        uint4 pk = make_uint4(*(uint32_t*)&p0, *(uint32_t*)&p1,
                              *(uint32_t*)&p2, *(uint32_t*)&p3);
        ((uint4*)g_Fbf)[i] = pk;
    }
    for (int i = gid; i < 1024 * K1; i += stride) {
        int n = i >> 9, k = i & 511;
        g_BT1[i] = __float2bfloat16(dW1[k * 1024 + n]);
    }
    for (int i = gid; i < 32 * K1; i += stride) {
        int n = i >> 9, k = i & 511;
        g_BTf[i] = __float2bfloat16(cW1[(4 + k) * 32 + n]);
    }
    for (int i = gid; i < 512 * K2; i += stride) {
        int n = i >> 10, k = i & 1023;
        g_BT2[i] = __float2bfloat16(dW2[k * 512 + n]);
    }
    for (int i = gid; i < MROWS; i += stride) g_depth[i] = 0.f;
}

// ---------------- 3-stage, 1-sync mma.sync GEMM ----------------------------
// Block tile 128x128, 8 warps (2x4), warp tile 64x32, K chunks of 64.
// MODE 0: C(bf16) = relu(A@B^T + bias)
// MODE 1: atomicAdd(g_depth[row], sum_n relu(A@B^T + bias)[n] * w3[n])
template <int MODE>
__global__ void __launch_bounds__(256, 2)
gemm_db(const __nv_bfloat16* __restrict__ A, int lda,
        const __nv_bfloat16* __restrict__ BT, int ldb,
        const float* __restrict__ bias,
        __nv_bfloat16* __restrict__ C, int ldc,
        int K, const float* __restrict__ w3)
{
    extern __shared__ __align__(16) char smem[];
    __shared__ float sAux[128];
    __shared__ float sW3[128];

    const int tid  = threadIdx.x;
    const int wid  = tid >> 5, lane = tid & 31;
    const int wm   = wid >> 2;          // 0..1 -> 64-row slab
    const int wn   = wid & 3;           // 0..3 -> 32-col slab
    const int m0   = blockIdx.y * 128;
    const int n0   = blockIdx.x * 128;

    if (tid < 128) sAux[tid] = bias[n0 + tid];
    if (MODE == 1 && tid < 128) sW3[tid] = w3[n0 + tid];

    const uint32_t smbase = s2u(smem);
    const uint32_t aAoff = ((wm * 64 + (lane & 15)) * SPAD + (lane >> 4) * 8) << 1;
    const uint32_t aBoff = BUFBYTES +
        ((((wn * 32 + (lane & 7)) * SPAD) + ((lane >> 3) & 1) * 8) << 1);

    const int srow = tid >> 3, soc = tid & 7;       // stage coords (32 rows/iter)

    const __nv_bfloat16* Ap0 = A + (size_t)m0 * lda;
    const __nv_bfloat16* Bp0 = BT + (size_t)n0 * ldb;
    const int nch = K >> 6;

    // stage chunk t into buffer t%3
    auto issue = [&](int t) {
        const int k0 = t << 6;
        const uint32_t sa = smbase + (uint32_t)(t % 3) * STG;
#pragma unroll
        for (int i = 0; i < 4; i++) {
            int row = srow + i * 32;
            cpa16(sa + ((row * SPAD + soc * 8) << 1), Ap0 + (size_t)row * lda + k0 + soc * 8);
        }
#pragma unroll
        for (int i = 0; i < 4; i++) {
            int row = srow + i * 32;
            cpa16(sa + BUFBYTES + ((row * SPAD + soc * 8) << 1),
                  Bp0 + (size_t)row * ldb + k0 + soc * 8);
        }
    };

    float acc[4][4][4];
#pragma unroll
    for (int i = 0; i < 4; i++)
#pragma unroll
        for (int j = 0; j < 4; j++)
#pragma unroll
            for (int k = 0; k < 4; k++) acc[i][j][k] = 0.f;

    // prologue: 2 chunks ahead
    issue(0); cp_commit();
    issue(1); cp_commit();

    for (int ch = 0; ch < nch; ch++) {
        cp_wait<1>();          // chunk ch complete (this thread's view)
        __syncthreads();       // publish; all warps done reading stage (ch+2)%3
        if (ch + 2 < nch) issue(ch + 2);
        cp_commit();

        const uint32_t boff = smbase + (uint32_t)(ch % 3) * STG;
#pragma unroll
        for (int ks = 0; ks < 4; ks++) {
            uint32_t af[4][4], bf[4][2];
#pragma unroll
            for (int mt = 0; mt < 4; mt++)
                ldmat_x4(af[mt], boff + aAoff + ((mt * 16 * SPAD + ks * 16) << 1));
#pragma unroll
            for (int nt = 0; nt < 4; nt++)
                ldmat_x2(bf[nt], boff + aBoff + ((nt * 8 * SPAD + ks * 16) << 1));
#pragma unroll
            for (int mt = 0; mt < 4; mt++)
#pragma unroll
                for (int nt = 0; nt < 4; nt++)
                    mma16816(acc[mt][nt], af[mt], bf[nt]);
        }
    }

    // ------------------------------ epilogue -------------------------------
    const int rbase = m0 + wm * 64 + (lane >> 2);
    const int clocal0 = wn * 32 + (lane & 3) * 2;

    if (MODE == 0) {
#pragma unroll
        for (int mt = 0; mt < 4; mt++) {
            int r0 = rbase + mt * 16;
#pragma unroll
            for (int nt = 0; nt < 4; nt++) {
                int cl = clocal0 + nt * 8;
                float b0 = sAux[cl], b1 = sAux[cl + 1];
                float v0 = fmaxf(acc[mt][nt][0] + b0, 0.f);
                float v1 = fmaxf(acc[mt][nt][1] + b1, 0.f);
                float v2 = fmaxf(acc[mt][nt][2] + b0, 0.f);
                float v3 = fmaxf(acc[mt][nt][3] + b1, 0.f);
                *(__nv_bfloat162*)(C + (size_t)r0 * ldc + n0 + cl) =
                    __floats2bfloat162_rn(v0, v1);
                *(__nv_bfloat162*)(C + (size_t)(r0 + 8) * ldc + n0 + cl) =
                    __floats2bfloat162_rn(v2, v3);
            }
        }
    } else {
#pragma unroll
        for (int mt = 0; mt < 4; mt++) {
            float s0 = 0.f, s1 = 0.f;
#pragma unroll
            for (int nt = 0; nt < 4; nt++) {
                int cl = clocal0 + nt * 8;
                float b0 = sAux[cl], b1 = sAux[cl + 1];
                float w0 = sW3[cl],  w1 = sW3[cl + 1];
                s0 += fmaxf(acc[mt][nt][0] + b0, 0.f) * w0
                    + fmaxf(acc[mt][nt][1] + b1, 0.f) * w1;
                s1 += fmaxf(acc[mt][nt][2] + b0, 0.f) * w0
                    + fmaxf(acc[mt][nt][3] + b1, 0.f) * w1;
            }
            s0 += __shfl_xor_sync(0xffffffffu, s0, 1);
            s0 += __shfl_xor_sync(0xffffffffu, s0, 2);
            s1 += __shfl_xor_sync(0xffffffffu, s1, 1);
            s1 += __shfl_xor_sync(0xffffffffu, s1, 2);
            if ((lane & 3) == 0) {
                int r0 = rbase + mt * 16;
                atomicAdd(&g_depth[r0], s0);
                atomicAdd(&g_depth[r0 + 8], s1);
            }
        }
    }
}

// ------------------------------- fproj -------------------------------------
// g_fproj[204800,32] = Fbf @ BTf^T + cb1.  Block 128 rows, warp tile 16x32.
__global__ void __launch_bounds__(256, 2)
fproj_kernel(const __nv_bfloat16* __restrict__ Fbf,
             const __nv_bfloat16* __restrict__ BTf,
             const float* __restrict__ cb1)
{
    __shared__ __align__(16) __nv_bfloat16 sA[128 * SPAD];   // 18 KB
    __shared__ __align__(16) __nv_bfloat16 sB[32 * SPAD];    // 4.5 KB
    __shared__ float sCb[32];

    const int tid = threadIdx.x;
    const int wid = tid >> 5, lane = tid & 31;
    const int m0 = blockIdx.x * 128;

    if (tid < 32) sCb[tid] = cb1[tid];

    const uint32_t aA = s2u(sA), aB = s2u(sB);
    const uint32_t aAf = aA + (((wid * 16 + (lane & 15)) * SPAD + (lane >> 4) * 8) << 1);
    const uint32_t aBf = aB + (((lane & 7) * SPAD + ((lane >> 3) & 1) * 8) << 1);

    float acc[4][4];
#pragma unroll
    for (int i = 0; i < 4; i++)
#pragma unroll
        for (int j = 0; j < 4; j++) acc[i][j] = 0.f;

    for (int ch = 0; ch < 8; ch++) {
        const int k0 = ch << 6;
        __syncthreads();
#pragma unroll
        for (int i = 0; i < 4; i++) {
            int q = i * 256 + tid, row = q >> 3, oc = q & 7;
            *(uint4*)&sA[row * SPAD + oc * 8] =
                *(const uint4*)(Fbf + (size_t)(m0 + row) * K1 + k0 + oc * 8);
        }
        {
            int row = tid >> 3, oc = tid & 7;
            *(uint4*)&sB[row * SPAD + oc * 8] =
                *(const uint4*)(BTf + (size_t)row * K1 + k0 + oc * 8);
        }
        __syncthreads();
#pragma unroll
        for (int ks = 0; ks < 4; ks++) {
            uint32_t af[4];
            ldmat_x4(af, aAf + (ks * 16 << 1));
#pragma unroll
            for (int nt = 0; nt < 4; nt++) {
                uint32_t bf[2];
                ldmat_x2(bf, aBf + ((nt * 8 * SPAD + ks * 16) << 1));
                mma16816(acc[nt], af, bf);
            }
        }
    }

    const int r = m0 + wid * 16 + (lane >> 2);
    const int c = (lane & 3) * 2;
#pragma unroll
    for (int nt = 0; nt < 4; nt++) {
        int col = c + nt * 8;
        float b0 = sCb[col], b1 = sCb[col + 1];
        *(float2*)&g_fproj[(size_t)r * 32 + col] =
            make_float2(acc[nt][0] + b0, acc[nt][1] + b1);
        *(float2*)&g_fproj[(size_t)(r + 8) * 32 + col] =
            make_float2(acc[nt][2] + b0, acc[nt][3] + b1);
    }
}

// ------------------------------- bones -------------------------------------
// 4 batches per block (64 threads each), 3 refinement iterations in smem.
__global__ void __launch_bounds__(256)
bones_kernel(const float* __restrict__ poses2d, const float* __restrict__ conf,
             const float* __restrict__ cW1, const float* __restrict__ cW2,
             const float* __restrict__ cb2, const float* __restrict__ cW3,
             const float* __restrict__ cb3, const float* __restrict__ db3,
             float* __restrict__ out)
{
    __shared__ float w1[4][32];
    __shared__ float w2[32][64];
    __shared__ float b2[64];
    __shared__ float w3s[64][3];
    __shared__ float b3[3];
    __shared__ float p3[4][75];
    __shared__ float cf[4][25];
    __shared__ float basef[4][16][32];
    __shared__ float dir4[4][16][4];
    __shared__ float g1[4][16][32];
    __shared__ float g2[4][16][64];
    __shared__ float bfm[4][16][3];
    __shared__ float upd[4][3];

    const int tid = threadIdx.x;
    const int u = tid >> 6, t = tid & 63;
    const size_t rowbase = ((size_t)blockIdx.x * 4 + u) * 25;

    if (tid < 128) ((float*)w1)[tid] = cW1[tid];
    for (int idx = tid; idx < 2048; idx += 256) ((float*)w2)[idx] = cW2[idx];
    if (tid < 64)  b2[tid] = cb2[tid];
    if (tid < 192) ((float*)w3s)[tid] = cW3[tid];
    if (tid < 3)   b3[tid] = cb3[tid];

    const float db3v = db3[0];
    if (t < 25) cf[u][t] = conf[rowbase + t];
    for (int idx = t; idx < 75; idx += 64) {
        int j = idx / 3, c = idx - j * 3;
        p3[u][idx] = (c < 2) ? poses2d[(rowbase + j) * 2 + c]
                             : (g_depth[rowbase + j] + db3v);
    }
    for (int idx = t; idx < 512; idx += 64) {
        int bone = idx >> 5, n = idx & 31;
        float fp = g_fproj[(rowbase + c_par[bone]) * 32 + n];
        float fc = g_fproj[(rowbase + c_chi[bone]) * 32 + n];
        basef[u][bone][n] = 0.5f * (fp + fc);
    }
    __syncthreads();

    for (int it = 0; it < 3; it++) {
        if (t < 16) {
            int p = c_par[t], c = c_chi[t];
            float vx = p3[u][c * 3 + 0] - p3[u][p * 3 + 0];
            float vy = p3[u][c * 3 + 1] - p3[u][p * 3 + 1];
            float vz = p3[u][c * 3 + 2] - p3[u][p * 3 + 2];
            float len = sqrtf(vx * vx + vy * vy + vz * vz);
            float inv = 1.f / (len + 1e-8f);
            dir4[u][t][0] = vx * inv;
            dir4[u][t][1] = vy * inv;
            dir4[u][t][2] = vz * inv;
            dir4[u][t][3] = len;
        }
        __syncthreads();
        for (int idx = t; idx < 512; idx += 64) {
            int bone = idx >> 5, n = idx & 31;
            float v = basef[u][bone][n]
                    + dir4[u][bone][0] * w1[0][n] + dir4[u][bone][1] * w1[1][n]
                    + dir4[u][bone][2] * w1[2][n] + dir4[u][bone][3] * w1[3][n];
            g1[u][bone][n] = fmaxf(v, 0.f);
        }
        __syncthreads();
        for (int idx = t; idx < 1024; idx += 64) {
            int bone = idx >> 6, n = idx & 63;
            float s = b2[n];
#pragma unroll
            for (int i = 0; i < 32; i++) s += g1[u][bone][i] * w2[i][n];
            g2[u][bone][n] = fmaxf(s, 0.f);
        }
        __syncthreads();
        if (t < 48) {
            int bone = t / 3, c = t - bone * 3;
            float s = b3[c];
#pragma unroll
            for (int i = 0; i < 64; i++) s += g2[u][bone][i] * w3s[i][c];
            bfm[u][bone][c] = s;
        }
        __syncthreads();
        if (t < 3) {
            float s = 0.f;
#pragma unroll
            for (int bone = 0; bone < 16; bone++) s += bfm[u][bone][t];
            upd[u][t] = 0.1f * (s * (1.f / 16.f));
        }
        __syncthreads();
        for (int idx = t; idx < 75; idx += 64) {
            int j = idx / 3, c = idx - j * 3;
            p3[u][idx] = (p3[u][idx] + upd[u][c]) * cf[u][j];
        }
        __syncthreads();
    }

    for (int idx = t; idx < 75; idx += 64) out[rowbase * 3 + idx] = p3[u][idx];
}

// ------------------------------ launcher -----------------------------------
extern "C" void kernel_launch(void* const* d_in, const int* in_sizes, int n_in,
                              void* d_out, int out_size) {
    (void)in_sizes; (void)n_in; (void)out_size;
    const float* poses2d  = (const float*)d_in[0];
    const float* features = (const float*)d_in[1];
    const float* conf     = (const float*)d_in[2];
    const float* dW1 = (const float*)d_in[3];
    const float* db1 = (const float*)d_in[4];
    const float* dW2 = (const float*)d_in[5];
    const float* db2 = (const float*)d_in[6];
    const float* dW3 = (const float*)d_in[7];
    const float* db3 = (const float*)d_in[8];
    const float* cW1 = (const float*)d_in[9];
    const float* cb1 = (const float*)d_in[10];
    const float* cW2 = (const float*)d_in[11];
    const float* cb2 = (const float*)d_in[12];
    const float* cW3 = (const float*)d_in[13];
    const float* cb3 = (const float*)d_in[14];
    float* out = (float*)d_out;

    __nv_bfloat16 *pFbf, *pBT1, *pBTf, *pBT2, *pH1;
    cudaGetSymbolAddress((void**)&pFbf, g_Fbf);
    cudaGetSymbolAddress((void**)&pBT1, g_BT1);
    cudaGetSymbolAddress((void**)&pBTf, g_BTf);
    cudaGetSymbolAddress((void**)&pBT2, g_BT2);
    cudaGetSymbolAddress((void**)&pH1, g_H1);

    cudaFuncSetAttribute(gemm_db<0>, cudaFuncAttributeMaxDynamicSharedMemorySize, GEMM_SMEM);
    cudaFuncSetAttribute(gemm_db<1>, cudaFuncAttributeMaxDynamicSharedMemorySize, GEMM_SMEM);

    // 1) convert features + transpose weights + zero depth
    prep_kernel<<<8192, 256>>>(features, dW1, dW2, cW1);

    // 2) GEMM1: H1 = relu(Fbf @ dW1 + db1)  (bf16 out, N=1024)
    gemm_db<0><<<dim3(8, MROWS / 128), 256, GEMM_SMEM>>>(
        pFbf, K1, pBT1, K1, db1, pH1, 1024, K1, nullptr);

    // 3) fproj: g_fproj = Fbf @ cW1[4:] + cb1  (f32, N=32)
    fproj_kernel<<<MROWS / 128, 256>>>(pFbf, pBTf, cb1);

    // 4) GEMM2 fused GEMV: depth += relu(H1@dW2+db2) @ dW3
    gemm_db<1><<<dim3(4, MROWS / 128), 256, GEMM_SMEM>>>(
        pH1, K2, pBT2, K2, db2, nullptr, 0, K2, dW3);

    // 5) skeletal refinement (adds db3 to depth)
    bones_kernel<<<2048, 256>>>(poses2d, conf, cW1, cW2, cb2, cW3, cb3, db3, out);
}

// round 15
// speedup vs baseline: 1.0909x; 1.0549x over previous
#include <cuda_runtime.h>
#include <cuda_bf16.h>
#include <cstdint>

// ---------------------------------------------------------------------------
// KITRO via warp-level bf16 mma.sync (HMMA.16816), cp.async double-buffered
// (exact R10 GEMM config: 128x128 tiles, 256 thr, 2 CTAs/SM, 2-stage).
// B=8192, J=25, FDIM=512, HDIM=1024.  M = B*J = 204800 rows.
//
// prep : features -> bf16 (g_Fbf), weights transposed to [n][k] bf16, depth=0
// GEMM1: H1[204800,1024](bf16) = relu(Fbf @ dW1 + db1)
// fproj: g_fproj[8192*17,32](f32) = Fbf[joints 0..16] @ cW1[4:] + cb1
// GEMM2 (fused GEMV): depth[m] += sum_n relu(H1@dW2+db2)[m,n] * dW3[n]
// bones: warp-per-batch (8/block), 3 refinement iterations, syncwarp-only.
// ---------------------------------------------------------------------------

#define MROWS 204800
#define FROWS (8192 * 17)             // 139264 packed fproj rows
#define K1    512
#define K2    1024
#define SPAD  72                      // smem row stride in bf16 (64 + 8 pad)
#define BUFELEM (128 * SPAD)          // 9216 bf16 per buffer
#define BUFBYTES (BUFELEM * 2)        // 18432
#define GEMM_SMEM (4 * BUFBYTES)      // 73728 bytes dynamic

__device__ __nv_bfloat16 g_Fbf[(size_t)MROWS * K1];    // 210 MB
__device__ __nv_bfloat16 g_BT1[1024 * K1];             // [n][k]
__device__ __nv_bfloat16 g_BTf[32 * K1];               // [n][k] fproj weights
__device__ __nv_bfloat16 g_BT2[512 * K2];              // [n][k]
__device__ __nv_bfloat16 g_H1[(size_t)MROWS * 1024];   // 420 MB
__device__ float         g_fproj[(size_t)FROWS * 32];  // 17.8 MB
__device__ float         g_depth[MROWS];

__constant__ int c_par[16] = {0, 0, 0, 0, 0, 0, 5, 7, 6, 8, 5, 6, 11, 13, 12, 14};
__constant__ int c_chi[16] = {1, 2, 3, 4, 5, 6, 7, 9, 8, 10, 11, 12, 13, 15, 14, 16};

// ------------------------------ helpers ------------------------------------
__device__ __forceinline__ uint32_t s2u(const void* p) {
    uint32_t a;
    asm("{ .reg .u64 t; cvta.to.shared.u64 t, %1; cvt.u32.u64 %0, t; }"
        : "=r"(a) : "l"(p));
    return a;
}
__device__ __forceinline__ void ldmat_x4(uint32_t* r, uint32_t addr) {
    asm volatile("ldmatrix.sync.aligned.m8n8.x4.shared.b16 {%0,%1,%2,%3}, [%4];"
                 : "=r"(r[0]), "=r"(r[1]), "=r"(r[2]), "=r"(r[3]) : "r"(addr));
}
__device__ __forceinline__ void ldmat_x2(uint32_t* r, uint32_t addr) {
    asm volatile("ldmatrix.sync.aligned.m8n8.x2.shared.b16 {%0,%1}, [%2];"
                 : "=r"(r[0]), "=r"(r[1]) : "r"(addr));
}
__device__ __forceinline__ void mma16816(float* c, const uint32_t* a, const uint32_t* b) {
    asm volatile(
        "mma.sync.aligned.m16n8k16.row.col.f32.bf16.bf16.f32 "
        "{%0,%1,%2,%3}, {%4,%5,%6,%7}, {%8,%9}, {%0,%1,%2,%3};"
        : "+f"(c[0]), "+f"(c[1]), "+f"(c[2]), "+f"(c[3])
        : "r"(a[0]), "r"(a[1]), "r"(a[2]), "r"(a[3]), "r"(b[0]), "r"(b[1]));
}
__device__ __forceinline__ void cpa16(uint32_t dst, const void* src) {
    asm volatile("cp.async.cg.shared.global [%0], [%1], 16;" :: "r"(dst), "l"(src));
}
__device__ __forceinline__ void cp_commit() {
    asm volatile("cp.async.commit_group;" ::: "memory");
}
template <int N> __device__ __forceinline__ void cp_wait() {
    asm volatile("cp.async.wait_group %0;" :: "n"(N) : "memory");
}

// ------------------------------- prep --------------------------------------
__global__ void prep_kernel(const float* __restrict__ features,
                            const float* __restrict__ dW1,
                            const float* __restrict__ dW2,
                            const float* __restrict__ cW1) {
    const int gid = blockIdx.x * blockDim.x + threadIdx.x;
    const int stride = gridDim.x * blockDim.x;
    for (int i = gid; i < MROWS * K1 / 8; i += stride) {
        const float4 f0 = ((const float4*)features)[i * 2];
        const float4 f1 = ((const float4*)features)[i * 2 + 1];
        __nv_bfloat162 p0 = __floats2bfloat162_rn(f0.x, f0.y);
        __nv_bfloat162 p1 = __floats2bfloat162_rn(f0.z, f0.w);
        __nv_bfloat162 p2 = __floats2bfloat162_rn(f1.x, f1.y);
        __nv_bfloat162 p3 = __floats2bfloat162_rn(f1.z, f1.w);
        uint4 pk = make_uint4(*(uint32_t*)&p0, *(uint32_t*)&p1,
                              *(uint32_t*)&p2, *(uint32_t*)&p3);
        ((uint4*)g_Fbf)[i] = pk;
    }
    for (int i = gid; i < 1024 * K1; i += stride) {
        int n = i >> 9, k = i & 511;
        g_BT1[i] = __float2bfloat16(dW1[k * 1024 + n]);
    }
    for (int i = gid; i < 32 * K1; i += stride) {
        int n = i >> 9, k = i & 511;
        g_BTf[i] = __float2bfloat16(cW1[(4 + k) * 32 + n]);
    }
    for (int i = gid; i < 512 * K2; i += stride) {
        int n = i >> 10, k = i & 1023;
        g_BT2[i] = __float2bfloat16(dW2[k * 512 + n]);
    }
    for (int i = gid; i < MROWS; i += stride) g_depth[i] = 0.f;
}

// --------------------- double-buffered mma.sync GEMM (R10) -----------------
// Block tile 128x128, 8 warps (2x4), warp tile 64x32, K chunks of 64.
// MODE 0: C(bf16) = relu(A@B^T + bias)
// MODE 1: atomicAdd(g_depth[row], sum_n relu(A@B^T + bias)[n] * w3[n])
template <int MODE>
__global__ void __launch_bounds__(256, 2)
gemm_db(const __nv_bfloat16* __restrict__ A, int lda,
        const __nv_bfloat16* __restrict__ BT, int ldb,
        const float* __restrict__ bias,
        __nv_bfloat16* __restrict__ C, int ldc,
        int K, const float* __restrict__ w3)
{
    extern __shared__ __align__(16) __nv_bfloat16 smem[];
    __nv_bfloat16* sA = smem;                       // 2 buffers
    __nv_bfloat16* sB = smem + 2 * BUFELEM;         // 2 buffers
    __shared__ float sAux[128];
    __shared__ float sW3[128];

    const int tid  = threadIdx.x;
    const int wid  = tid >> 5, lane = tid & 31;
    const int wm   = wid >> 2;          // 0..1 -> 64-row slab
    const int wn   = wid & 3;           // 0..3 -> 32-col slab
    const int m0   = blockIdx.y * 128;
    const int n0   = blockIdx.x * 128;

    if (tid < 128) sAux[tid] = bias[n0 + tid];
    if (MODE == 1 && tid < 128) sW3[tid] = w3[n0 + tid];

    const uint32_t aA = s2u(sA), aB = s2u(sB);
    const uint32_t aAf = aA + (((wm * 64 + (lane & 15)) * SPAD + (lane >> 4) * 8) << 1);
    const uint32_t aBf = aB + (((wn * 32 + (lane & 7)) * SPAD + ((lane >> 3) & 1) * 8) << 1);

    const int srow = tid >> 3, soc = tid & 7;       // stage: 4 iters x 256 thr

    float acc[4][4][4];
#pragma unroll
    for (int i = 0; i < 4; i++)
#pragma unroll
        for (int j = 0; j < 4; j++)
#pragma unroll
            for (int k = 0; k < 4; k++) acc[i][j][k] = 0.f;

    const int nch = K >> 6;

    // prologue: stage chunk 0 into buffer 0
    {
        const __nv_bfloat16* Ap = A + (size_t)m0 * lda;
        const __nv_bfloat16* Bp = BT + (size_t)n0 * ldb;
#pragma unroll
        for (int i = 0; i < 4; i++) {
            int row = srow + i * 32;
            cpa16(aA + ((row * SPAD + soc * 8) << 1), Ap + (size_t)row * lda + soc * 8);
        }
#pragma unroll
        for (int i = 0; i < 4; i++) {
            int row = srow + i * 32;
            cpa16(aB + ((row * SPAD + soc * 8) << 1), Bp + (size_t)row * ldb + soc * 8);
        }
        cp_commit();
    }

    for (int ch = 0; ch < nch; ch++) {
        if (ch + 1 < nch) {
            const int nb = (ch + 1) & 1;
            const int k0 = (ch + 1) << 6;
            const __nv_bfloat16* Ap = A + (size_t)m0 * lda + k0;
            const __nv_bfloat16* Bp = BT + (size_t)n0 * ldb + k0;
#pragma unroll
            for (int i = 0; i < 4; i++) {
                int row = srow + i * 32;
                cpa16(aA + nb * BUFBYTES + ((row * SPAD + soc * 8) << 1),
                      Ap + (size_t)row * lda + soc * 8);
            }
#pragma unroll
            for (int i = 0; i < 4; i++) {
                int row = srow + i * 32;
                cpa16(aB + nb * BUFBYTES + ((row * SPAD + soc * 8) << 1),
                      Bp + (size_t)row * ldb + soc * 8);
            }
            cp_commit();
            cp_wait<1>();
        } else {
            cp_wait<0>();
        }
        __syncthreads();

        const uint32_t boff = (ch & 1) * BUFBYTES;
#pragma unroll
        for (int ks = 0; ks < 4; ks++) {
            uint32_t af[4][4], bf[4][2];
#pragma unroll
            for (int mt = 0; mt < 4; mt++)
                ldmat_x4(af[mt], aAf + boff + ((mt * 16 * SPAD + ks * 16) << 1));
#pragma unroll
            for (int nt = 0; nt < 4; nt++)
                ldmat_x2(bf[nt], aBf + boff + ((nt * 8 * SPAD + ks * 16) << 1));
#pragma unroll
            for (int mt = 0; mt < 4; mt++)
#pragma unroll
                for (int nt = 0; nt < 4; nt++)
                    mma16816(acc[mt][nt], af[mt], bf[nt]);
        }
        __syncthreads();
    }

    // ------------------------------ epilogue -------------------------------
    const int rbase = m0 + wm * 64 + (lane >> 2);
    const int clocal0 = wn * 32 + (lane & 3) * 2;

    if (MODE == 0) {
#pragma unroll
        for (int mt = 0; mt < 4; mt++) {
            int r0 = rbase + mt * 16;
#pragma unroll
            for (int nt = 0; nt < 4; nt++) {
                int cl = clocal0 + nt * 8;
                float b0 = sAux[cl], b1 = sAux[cl + 1];
                float v0 = fmaxf(acc[mt][nt][0] + b0, 0.f);
                float v1 = fmaxf(acc[mt][nt][1] + b1, 0.f);
                float v2 = fmaxf(acc[mt][nt][2] + b0, 0.f);
                float v3 = fmaxf(acc[mt][nt][3] + b1, 0.f);
                *(__nv_bfloat162*)(C + (size_t)r0 * ldc + n0 + cl) =
                    __floats2bfloat162_rn(v0, v1);
                *(__nv_bfloat162*)(C + (size_t)(r0 + 8) * ldc + n0 + cl) =
                    __floats2bfloat162_rn(v2, v3);
            }
        }
    } else {
#pragma unroll
        for (int mt = 0; mt < 4; mt++) {
            float s0 = 0.f, s1 = 0.f;
#pragma unroll
            for (int nt = 0; nt < 4; nt++) {
                int cl = clocal0 + nt * 8;
                float b0 = sAux[cl], b1 = sAux[cl + 1];
                float w0 = sW3[cl],  w1 = sW3[cl + 1];
                s0 += fmaxf(acc[mt][nt][0] + b0, 0.f) * w0
                    + fmaxf(acc[mt][nt][1] + b1, 0.f) * w1;
                s1 += fmaxf(acc[mt][nt][2] + b0, 0.f) * w0
                    + fmaxf(acc[mt][nt][3] + b1, 0.f) * w1;
            }
            s0 += __shfl_xor_sync(0xffffffffu, s0, 1);
            s0 += __shfl_xor_sync(0xffffffffu, s0, 2);
            s1 += __shfl_xor_sync(0xffffffffu, s1, 1);
            s1 += __shfl_xor_sync(0xffffffffu, s1, 2);
            if ((lane & 3) == 0) {
                int r0 = rbase + mt * 16;
                atomicAdd(&g_depth[r0], s0);
                atomicAdd(&g_depth[r0 + 8], s1);
            }
        }
    }
}

// ------------------------------- fproj -------------------------------------
// Packed rows: i -> batch i/17, joint i%17 (only joints 0..16 are used by
// bones).  g_fproj[i,32] = Fbf[(i/17)*25 + i%17] @ BTf^T + cb1.
__global__ void __launch_bounds__(256, 2)
fproj_kernel(const __nv_bfloat16* __restrict__ Fbf,
             const __nv_bfloat16* __restrict__ BTf,
             const float* __restrict__ cb1)
{
    __shared__ __align__(16) __nv_bfloat16 sA[128 * SPAD];   // 18 KB
    __shared__ __align__(16) __nv_bfloat16 sB[32 * SPAD];    // 4.5 KB
    __shared__ float sCb[32];

    const int tid = threadIdx.x;
    const int wid = tid >> 5, lane = tid & 31;
    const int m0 = blockIdx.x * 128;

    if (tid < 32) sCb[tid] = cb1[tid];

    const uint32_t aA = s2u(sA), aB = s2u(sB);
    const uint32_t aAf = aA + (((wid * 16 + (lane & 15)) * SPAD + (lane >> 4) * 8) << 1);
    const uint32_t aBf = aB + (((lane & 7) * SPAD + ((lane >> 3) & 1) * 8) << 1);

    float acc[4][4];
#pragma unroll
    for (int i = 0; i < 4; i++)
#pragma unroll
        for (int j = 0; j < 4; j++) acc[i][j] = 0.f;

    for (int ch = 0; ch < 8; ch++) {
        const int k0 = ch << 6;
        __syncthreads();
#pragma unroll
        for (int i = 0; i < 4; i++) {
            int q = i * 256 + tid, row = q >> 3, oc = q & 7;
            int gp = m0 + row;
            int fr = (gp / 17) * 25 + (gp % 17);
            *(uint4*)&sA[row * SPAD + oc * 8] =
                *(const uint4*)(Fbf + (size_t)fr * K1 + k0 + oc * 8);
        }
        {
            int row = tid >> 3, oc = tid & 7;
            *(uint4*)&sB[row * SPAD + oc * 8] =
                *(const uint4*)(BTf + (size_t)row * K1 + k0 + oc * 8);
        }
        __syncthreads();
#pragma unroll
        for (int ks = 0; ks < 4; ks++) {
            uint32_t af[4];
            ldmat_x4(af, aAf + (ks * 16 << 1));
#pragma unroll
            for (int nt = 0; nt < 4; nt++) {
                uint32_t bf[2];
                ldmat_x2(bf, aBf + ((nt * 8 * SPAD + ks * 16) << 1));
                mma16816(acc[nt], af, bf);
            }
        }
    }

    const int r = m0 + wid * 16 + (lane >> 2);
    const int c = (lane & 3) * 2;
#pragma unroll
    for (int nt = 0; nt < 4; nt++) {
        int col = c + nt * 8;
        float b0 = sCb[col], b1 = sCb[col + 1];
        *(float2*)&g_fproj[(size_t)r * 32 + col] =
            make_float2(acc[nt][0] + b0, acc[nt][1] + b1);
        *(float2*)&g_fproj[(size_t)(r + 8) * 32 + col] =
            make_float2(acc[nt][2] + b0, acc[nt][3] + b1);
    }
}

// ------------------------------- bones -------------------------------------
// Warp-per-batch: 8 batches per 256-thread block; weights loaded once, then
// the 3-iteration loop uses ONLY __syncwarp (no block barriers).
// Dynamic smem layout (floats):
//   [0..128)    w1      [128..2176)  w2     [2176..2240) b2
//   [2240..2432) w3     [2432..2436) b3
//   per-warp u at 2436 + u*2272:
//     p3:+0(76)  cf:+76(28)  basef:+104(512)  g1:+616(512)
//     g2:+1128(1024)  dir4:+2152(64)  bfm:+2216(48)  upd:+2264(4)
#define BONES_SMEM ((2436 + 8 * 2272) * 4)
__global__ void __launch_bounds__(256)
bones_kernel(const float* __restrict__ poses2d, const float* __restrict__ conf,
             const float* __restrict__ cW1, const float* __restrict__ cW2,
             const float* __restrict__ cb2, const float* __restrict__ cW3,
             const float* __restrict__ cb3, const float* __restrict__ db3,
             float* __restrict__ out)
{
    extern __shared__ float bs[];
    float* w1  = bs;            // [4][32]
    float* w2  = bs + 128;      // [32][64]
    float* b2  = bs + 2176;     // [64]
    float* w3s = bs + 2240;     // [64][3]
    float* b3  = bs + 2432;     // [3]

    const int tid = threadIdx.x;
    const int u = tid >> 5, lane = tid & 31;

    if (tid < 128) w1[tid] = cW1[tid];
    for (int idx = tid; idx < 2048; idx += 256) w2[idx] = cW2[idx];
    if (tid < 64)  b2[tid] = cb2[tid];
    if (tid < 192) w3s[tid] = cW3[tid];
    if (tid < 3)   b3[tid] = cb3[tid];
    __syncthreads();            // only block barrier

    float* pw    = bs + 2436 + u * 2272;
    float* p3    = pw;          // [75]
    float* cf    = pw + 76;     // [25]
    float* basef = pw + 104;    // [16][32]
    float* g1    = pw + 616;    // [16][32]
    float* g2    = pw + 1128;   // [16][64]
    float* dir4  = pw + 2152;   // [16][4]
    float* bfm   = pw + 2216;   // [16][3]
    float* upd   = pw + 2264;   // [3]

    const int batch = blockIdx.x * 8 + u;
    const size_t rowbase = (size_t)batch * 25;
    const size_t fbase   = (size_t)batch * 17;

    const float db3v = db3[0];
    if (lane < 25) cf[lane] = conf[rowbase + lane];
    for (int idx = lane; idx < 75; idx += 32) {
        int j = idx / 3, c = idx - j * 3;
        p3[idx] = (c < 2) ? poses2d[(rowbase + j) * 2 + c]
                          : (g_depth[rowbase + j] + db3v);
    }
    for (int idx = lane; idx < 512; idx += 32) {
        int bone = idx >> 5, n = idx & 31;
        float fp = g_fproj[(fbase + c_par[bone]) * 32 + n];
        float fc = g_fproj[(fbase + c_chi[bone]) * 32 + n];
        basef[idx] = 0.5f * (fp + fc);
    }
    __syncwarp();

    for (int it = 0; it < 3; it++) {
        if (lane < 16) {
            int p = c_par[lane], c = c_chi[lane];
            float vx = p3[c * 3 + 0] - p3[p * 3 + 0];
            float vy = p3[c * 3 + 1] - p3[p * 3 + 1];
            float vz = p3[c * 3 + 2] - p3[p * 3 + 2];
            float len = sqrtf(vx * vx + vy * vy + vz * vz);
            float inv = 1.f / (len + 1e-8f);
            dir4[lane * 4 + 0] = vx * inv;
            dir4[lane * 4 + 1] = vy * inv;
            dir4[lane * 4 + 2] = vz * inv;
            dir4[lane * 4 + 3] = len;
        }
        __syncwarp();
        for (int idx = lane; idx < 512; idx += 32) {
            int bone = idx >> 5, n = idx & 31;
            float v = basef[idx]
                    + dir4[bone * 4 + 0] * w1[n]       + dir4[bone * 4 + 1] * w1[32 + n]
                    + dir4[bone * 4 + 2] * w1[64 + n]  + dir4[bone * 4 + 3] * w1[96 + n];
            g1[idx] = fmaxf(v, 0.f);
        }
        __syncwarp();
        for (int idx = lane; idx < 1024; idx += 32) {
            int bone = idx >> 6, n = idx & 63;
            float s = b2[n];
            const float* g1b = g1 + bone * 32;
#pragma unroll
            for (int i = 0; i < 32; i++) s += g1b[i] * w2[i * 64 + n];
            g2[idx] = fmaxf(s, 0.f);
        }
        __syncwarp();
        for (int idx = lane; idx < 48; idx += 32) {
            int bone = idx / 3, c = idx - bone * 3;
            float s = b3[c];
            const float* g2b = g2 + bone * 64;
#pragma unroll
            for (int i = 0; i < 64; i++) s += g2b[i] * w3s[i * 3 + c];
            bfm[idx] = s;
        }
        __syncwarp();
        if (lane < 3) {
            float s = 0.f;
#pragma unroll
            for (int bone = 0; bone < 16; bone++) s += bfm[bone * 3 + lane];
            upd[lane] = 0.1f * (s * (1.f / 16.f));
        }
        __syncwarp();
        for (int idx = lane; idx < 75; idx += 32) {
            int j = idx / 3, c = idx - j * 3;
            p3[idx] = (p3[idx] + upd[c]) * cf[j];
        }
        __syncwarp();
    }

    for (int idx = lane; idx < 75; idx += 32) out[rowbase * 3 + idx] = p3[idx];
}

// ------------------------------ launcher -----------------------------------
extern "C" void kernel_launch(void* const* d_in, const int* in_sizes, int n_in,
                              void* d_out, int out_size) {
    (void)in_sizes; (void)n_in; (void)out_size;
    const float* poses2d  = (const float*)d_in[0];
    const float* features = (const float*)d_in[1];
    const float* conf     = (const float*)d_in[2];
    const float* dW1 = (const float*)d_in[3];
    const float* db1 = (const float*)d_in[4];
    const float* dW2 = (const float*)d_in[5];
    const float* db2 = (const float*)d_in[6];
    const float* dW3 = (const float*)d_in[7];
    const float* db3 = (const float*)d_in[8];
    const float* cW1 = (const float*)d_in[9];
    const float* cb1 = (const float*)d_in[10];
    const float* cW2 = (const float*)d_in[11];
    const float* cb2 = (const float*)d_in[12];
    const float* cW3 = (const float*)d_in[13];
    const float* cb3 = (const float*)d_in[14];
    float* out = (float*)d_out;

    __nv_bfloat16 *pFbf, *pBT1, *pBTf, *pBT2, *pH1;
    cudaGetSymbolAddress((void**)&pFbf, g_Fbf);
    cudaGetSymbolAddress((void**)&pBT1, g_BT1);
    cudaGetSymbolAddress((void**)&pBTf, g_BTf);
    cudaGetSymbolAddress((void**)&pBT2, g_BT2);
    cudaGetSymbolAddress((void**)&pH1, g_H1);

    cudaFuncSetAttribute(gemm_db<0>, cudaFuncAttributeMaxDynamicSharedMemorySize, GEMM_SMEM);
    cudaFuncSetAttribute(gemm_db<1>, cudaFuncAttributeMaxDynamicSharedMemorySize, GEMM_SMEM);
    cudaFuncSetAttribute(bones_kernel, cudaFuncAttributeMaxDynamicSharedMemorySize, BONES_SMEM);

    // 1) convert features + transpose weights + zero depth
    prep_kernel<<<8192, 256>>>(features, dW1, dW2, cW1);

    // 2) GEMM1: H1 = relu(Fbf @ dW1 + db1)  (bf16 out, N=1024)
    gemm_db<0><<<dim3(8, MROWS / 128), 256, GEMM_SMEM>>>(
        pFbf, K1, pBT1, K1, db1, pH1, 1024, K1, nullptr);

    // 3) fproj (packed joints 0..16): g_fproj = Fbf[gather] @ cW1[4:] + cb1
    fproj_kernel<<<FROWS / 128, 256>>>(pFbf, pBTf, cb1);

    // 4) GEMM2 fused GEMV: depth += relu(H1@dW2+db2) @ dW3
    gemm_db<1><<<dim3(4, MROWS / 128), 256, GEMM_SMEM>>>(
        pH1, K2, pBT2, K2, db2, nullptr, 0, K2, dW3);

    // 5) skeletal refinement (adds db3 to depth), warp-per-batch
    bones_kernel<<<1024, 256, BONES_SMEM>>>(
        poses2d, conf, cW1, cW2, cb2, cW3, cb3, db3, out);
}

// round 16
// speedup vs baseline: 1.1661x; 1.0690x over previous
#include <cuda_runtime.h>
#include <cuda_bf16.h>
#include <cstdint>

// ---------------------------------------------------------------------------
// KITRO via warp-level bf16 mma.sync (HMMA.16816), cp.async double-buffered
// (frozen R10 GEMM config: 128x128 tiles, 256 thr, 2 CTAs/SM, 2-stage).
// B=8192, J=25, FDIM=512, HDIM=1024.  M = B*J = 204800 rows.
//
// prep : features -> bf16 (g_Fbf), weights transposed to [n][k] bf16, depth=0
// GEMM1: H1[204800,1024](bf16) = relu(Fbf @ dW1 + db1)
// fproj: (side stream, overlaps GEMMs) packed joints 0..16 @ cW1[4:] + cb1
// GEMM2 (fused GEMV): depth[m] += sum_n relu(H1@dW2+db2)[m,n] * dW3[n]
// bones: warp-per-batch, register-blocked g2, syncwarp-only inner loop.
// ---------------------------------------------------------------------------

#define MROWS 204800
#define FROWS (8192 * 17)             // 139264 packed fproj rows
#define K1    512
#define K2    1024
#define SPAD  72                      // smem row stride in bf16 (64 + 8 pad)
#define BUFELEM (128 * SPAD)          // 9216 bf16 per buffer
#define BUFBYTES (BUFELEM * 2)        // 18432
#define GEMM_SMEM (4 * BUFBYTES)      // 73728 bytes dynamic

__device__ __nv_bfloat16 g_Fbf[(size_t)MROWS * K1];    // 210 MB
__device__ __nv_bfloat16 g_BT1[1024 * K1];             // [n][k]
__device__ __nv_bfloat16 g_BTf[32 * K1];               // [n][k] fproj weights
__device__ __nv_bfloat16 g_BT2[512 * K2];              // [n][k]
__device__ __nv_bfloat16 g_H1[(size_t)MROWS * 1024];   // 420 MB
__device__ float         g_fproj[(size_t)FROWS * 32];  // 17.8 MB
__device__ float         g_depth[MROWS];

__constant__ int c_par[16] = {0, 0, 0, 0, 0, 0, 5, 7, 6, 8, 5, 6, 11, 13, 12, 14};
__constant__ int c_chi[16] = {1, 2, 3, 4, 5, 6, 7, 9, 8, 10, 11, 12, 13, 15, 14, 16};

// ------------------------------ helpers ------------------------------------
__device__ __forceinline__ uint32_t s2u(const void* p) {
    uint32_t a;
    asm("{ .reg .u64 t; cvta.to.shared.u64 t, %1; cvt.u32.u64 %0, t; }"
        : "=r"(a) : "l"(p));
    return a;
}
__device__ __forceinline__ void ldmat_x4(uint32_t* r, uint32_t addr) {
    asm volatile("ldmatrix.sync.aligned.m8n8.x4.shared.b16 {%0,%1,%2,%3}, [%4];"
                 : "=r"(r[0]), "=r"(r[1]), "=r"(r[2]), "=r"(r[3]) : "r"(addr));
}
__device__ __forceinline__ void ldmat_x2(uint32_t* r, uint32_t addr) {
    asm volatile("ldmatrix.sync.aligned.m8n8.x2.shared.b16 {%0,%1}, [%2];"
                 : "=r"(r[0]), "=r"(r[1]) : "r"(addr));
}
__device__ __forceinline__ void mma16816(float* c, const uint32_t* a, const uint32_t* b) {
    asm volatile(
        "mma.sync.aligned.m16n8k16.row.col.f32.bf16.bf16.f32 "
        "{%0,%1,%2,%3}, {%4,%5,%6,%7}, {%8,%9}, {%0,%1,%2,%3};"
        : "+f"(c[0]), "+f"(c[1]), "+f"(c[2]), "+f"(c[3])
        : "r"(a[0]), "r"(a[1]), "r"(a[2]), "r"(a[3]), "r"(b[0]), "r"(b[1]));
}
__device__ __forceinline__ void cpa16(uint32_t dst, const void* src) {
    asm volatile("cp.async.cg.shared.global [%0], [%1], 16;" :: "r"(dst), "l"(src));
}
__device__ __forceinline__ void cp_commit() {
    asm volatile("cp.async.commit_group;" ::: "memory");
}
template <int N> __device__ __forceinline__ void cp_wait() {
    asm volatile("cp.async.wait_group %0;" :: "n"(N) : "memory");
}

// ------------------------------- prep --------------------------------------
__global__ void prep_kernel(const float* __restrict__ features,
                            const float* __restrict__ dW1,
                            const float* __restrict__ dW2,
                            const float* __restrict__ cW1) {
    const int gid = blockIdx.x * blockDim.x + threadIdx.x;
    const int stride = gridDim.x * blockDim.x;
    for (int i = gid; i < MROWS * K1 / 8; i += stride) {
        const float4 f0 = ((const float4*)features)[i * 2];
        const float4 f1 = ((const float4*)features)[i * 2 + 1];
        __nv_bfloat162 p0 = __floats2bfloat162_rn(f0.x, f0.y);
        __nv_bfloat162 p1 = __floats2bfloat162_rn(f0.z, f0.w);
        __nv_bfloat162 p2 = __floats2bfloat162_rn(f1.x, f1.y);
        __nv_bfloat162 p3 = __floats2bfloat162_rn(f1.z, f1.w);
        uint4 pk = make_uint4(*(uint32_t*)&p0, *(uint32_t*)&p1,
                              *(uint32_t*)&p2, *(uint32_t*)&p3);
        ((uint4*)g_Fbf)[i] = pk;
    }
    for (int i = gid; i < 1024 * K1; i += stride) {
        int n = i >> 9, k = i & 511;
        g_BT1[i] = __float2bfloat16(dW1[k * 1024 + n]);
    }
    for (int i = gid; i < 32 * K1; i += stride) {
        int n = i >> 9, k = i & 511;
        g_BTf[i] = __float2bfloat16(cW1[(4 + k) * 32 + n]);
    }
    for (int i = gid; i < 512 * K2; i += stride) {
        int n = i >> 10, k = i & 1023;
        g_BT2[i] = __float2bfloat16(dW2[k * 512 + n]);
    }
    for (int i = gid; i < MROWS; i += stride) g_depth[i] = 0.f;
}

// --------------------- double-buffered mma.sync GEMM (R10) -----------------
// Block tile 128x128, 8 warps (2x4), warp tile 64x32, K chunks of 64.
// MODE 0: C(bf16) = relu(A@B^T + bias)
// MODE 1: atomicAdd(g_depth[row], sum_n relu(A@B^T + bias)[n] * w3[n])
template <int MODE>
__global__ void __launch_bounds__(256, 2)
gemm_db(const __nv_bfloat16* __restrict__ A, int lda,
        const __nv_bfloat16* __restrict__ BT, int ldb,
        const float* __restrict__ bias,
        __nv_bfloat16* __restrict__ C, int ldc,
        int K, const float* __restrict__ w3)
{
    extern __shared__ __align__(16) __nv_bfloat16 smem[];
    __nv_bfloat16* sA = smem;                       // 2 buffers
    __nv_bfloat16* sB = smem + 2 * BUFELEM;         // 2 buffers
    __shared__ float sAux[128];
    __shared__ float sW3[128];

    const int tid  = threadIdx.x;
    const int wid  = tid >> 5, lane = tid & 31;
    const int wm   = wid >> 2;          // 0..1 -> 64-row slab
    const int wn   = wid & 3;           // 0..3 -> 32-col slab
    const int m0   = blockIdx.y * 128;
    const int n0   = blockIdx.x * 128;

    if (tid < 128) sAux[tid] = bias[n0 + tid];
    if (MODE == 1 && tid < 128) sW3[tid] = w3[n0 + tid];

    const uint32_t aA = s2u(sA), aB = s2u(sB);
    const uint32_t aAf = aA + (((wm * 64 + (lane & 15)) * SPAD + (lane >> 4) * 8) << 1);
    const uint32_t aBf = aB + (((wn * 32 + (lane & 7)) * SPAD + ((lane >> 3) & 1) * 8) << 1);

    const int srow = tid >> 3, soc = tid & 7;       // stage: 4 iters x 256 thr

    float acc[4][4][4];
#pragma unroll
    for (int i = 0; i < 4; i++)
#pragma unroll
        for (int j = 0; j < 4; j++)
#pragma unroll
            for (int k = 0; k < 4; k++) acc[i][j][k] = 0.f;

    const int nch = K >> 6;

    // prologue: stage chunk 0 into buffer 0
    {
        const __nv_bfloat16* Ap = A + (size_t)m0 * lda;
        const __nv_bfloat16* Bp = BT + (size_t)n0 * ldb;
#pragma unroll
        for (int i = 0; i < 4; i++) {
            int row = srow + i * 32;
            cpa16(aA + ((row * SPAD + soc * 8) << 1), Ap + (size_t)row * lda + soc * 8);
        }
#pragma unroll
        for (int i = 0; i < 4; i++) {
            int row = srow + i * 32;
            cpa16(aB + ((row * SPAD + soc * 8) << 1), Bp + (size_t)row * ldb + soc * 8);
        }
        cp_commit();
    }

    for (int ch = 0; ch < nch; ch++) {
        if (ch + 1 < nch) {
            const int nb = (ch + 1) & 1;
            const int k0 = (ch + 1) << 6;
            const __nv_bfloat16* Ap = A + (size_t)m0 * lda + k0;
            const __nv_bfloat16* Bp = BT + (size_t)n0 * ldb + k0;
#pragma unroll
            for (int i = 0; i < 4; i++) {
                int row = srow + i * 32;
                cpa16(aA + nb * BUFBYTES + ((row * SPAD + soc * 8) << 1),
                      Ap + (size_t)row * lda + soc * 8);
            }
#pragma unroll
            for (int i = 0; i < 4; i++) {
                int row = srow + i * 32;
                cpa16(aB + nb * BUFBYTES + ((row * SPAD + soc * 8) << 1),
                      Bp + (size_t)row * ldb + soc * 8);
            }
            cp_commit();
            cp_wait<1>();
        } else {
            cp_wait<0>();
        }
        __syncthreads();

        const uint32_t boff = (ch & 1) * BUFBYTES;
#pragma unroll
        for (int ks = 0; ks < 4; ks++) {
            uint32_t af[4][4], bf[4][2];
#pragma unroll
            for (int mt = 0; mt < 4; mt++)
                ldmat_x4(af[mt], aAf + boff + ((mt * 16 * SPAD + ks * 16) << 1));
#pragma unroll
            for (int nt = 0; nt < 4; nt++)
                ldmat_x2(bf[nt], aBf + boff + ((nt * 8 * SPAD + ks * 16) << 1));
#pragma unroll
            for (int mt = 0; mt < 4; mt++)
#pragma unroll
                for (int nt = 0; nt < 4; nt++)
                    mma16816(acc[mt][nt], af[mt], bf[nt]);
        }
        __syncthreads();
    }

    // ------------------------------ epilogue -------------------------------
    const int rbase = m0 + wm * 64 + (lane >> 2);
    const int clocal0 = wn * 32 + (lane & 3) * 2;

    if (MODE == 0) {
#pragma unroll
        for (int mt = 0; mt < 4; mt++) {
            int r0 = rbase + mt * 16;
#pragma unroll
            for (int nt = 0; nt < 4; nt++) {
                int cl = clocal0 + nt * 8;
                float b0 = sAux[cl], b1 = sAux[cl + 1];
                float v0 = fmaxf(acc[mt][nt][0] + b0, 0.f);
                float v1 = fmaxf(acc[mt][nt][1] + b1, 0.f);
                float v2 = fmaxf(acc[mt][nt][2] + b0, 0.f);
                float v3 = fmaxf(acc[mt][nt][3] + b1, 0.f);
                *(__nv_bfloat162*)(C + (size_t)r0 * ldc + n0 + cl) =
                    __floats2bfloat162_rn(v0, v1);
                *(__nv_bfloat162*)(C + (size_t)(r0 + 8) * ldc + n0 + cl) =
                    __floats2bfloat162_rn(v2, v3);
            }
        }
    } else {
#pragma unroll
        for (int mt = 0; mt < 4; mt++) {
            float s0 = 0.f, s1 = 0.f;
#pragma unroll
            for (int nt = 0; nt < 4; nt++) {
                int cl = clocal0 + nt * 8;
                float b0 = sAux[cl], b1 = sAux[cl + 1];
                float w0 = sW3[cl],  w1 = sW3[cl + 1];
                s0 += fmaxf(acc[mt][nt][0] + b0, 0.f) * w0
                    + fmaxf(acc[mt][nt][1] + b1, 0.f) * w1;
                s1 += fmaxf(acc[mt][nt][2] + b0, 0.f) * w0
                    + fmaxf(acc[mt][nt][3] + b1, 0.f) * w1;
            }
            s0 += __shfl_xor_sync(0xffffffffu, s0, 1);
            s0 += __shfl_xor_sync(0xffffffffu, s0, 2);
            s1 += __shfl_xor_sync(0xffffffffu, s1, 1);
            s1 += __shfl_xor_sync(0xffffffffu, s1, 2);
            if ((lane & 3) == 0) {
                int r0 = rbase + mt * 16;
                atomicAdd(&g_depth[r0], s0);
                atomicAdd(&g_depth[r0 + 8], s1);
            }
        }
    }
}

// ------------------------------- fproj -------------------------------------
// Packed rows: i -> batch i/17, joint i%17 (only joints 0..16 are used by
// bones).  g_fproj[i,32] = Fbf[(i/17)*25 + i%17] @ BTf^T + cb1.
__global__ void __launch_bounds__(256, 2)
fproj_kernel(const __nv_bfloat16* __restrict__ Fbf,
             const __nv_bfloat16* __restrict__ BTf,
             const float* __restrict__ cb1)
{
    __shared__ __align__(16) __nv_bfloat16 sA[128 * SPAD];   // 18 KB
    __shared__ __align__(16) __nv_bfloat16 sB[32 * SPAD];    // 4.5 KB
    __shared__ float sCb[32];

    const int tid = threadIdx.x;
    const int wid = tid >> 5, lane = tid & 31;
    const int m0 = blockIdx.x * 128;

    if (tid < 32) sCb[tid] = cb1[tid];

    const uint32_t aA = s2u(sA), aB = s2u(sB);
    const uint32_t aAf = aA + (((wid * 16 + (lane & 15)) * SPAD + (lane >> 4) * 8) << 1);
    const uint32_t aBf = aB + (((lane & 7) * SPAD + ((lane >> 3) & 1) * 8) << 1);

    float acc[4][4];
#pragma unroll
    for (int i = 0; i < 4; i++)
#pragma unroll
        for (int j = 0; j < 4; j++) acc[i][j] = 0.f;

    for (int ch = 0; ch < 8; ch++) {
        const int k0 = ch << 6;
        __syncthreads();
#pragma unroll
        for (int i = 0; i < 4; i++) {
            int q = i * 256 + tid, row = q >> 3, oc = q & 7;
            int gp = m0 + row;
            int fr = (gp / 17) * 25 + (gp % 17);
            *(uint4*)&sA[row * SPAD + oc * 8] =
                *(const uint4*)(Fbf + (size_t)fr * K1 + k0 + oc * 8);
        }
        {
            int row = tid >> 3, oc = tid & 7;
            *(uint4*)&sB[row * SPAD + oc * 8] =
                *(const uint4*)(BTf + (size_t)row * K1 + k0 + oc * 8);
        }
        __syncthreads();
#pragma unroll
        for (int ks = 0; ks < 4; ks++) {
            uint32_t af[4];
            ldmat_x4(af, aAf + (ks * 16 << 1));
#pragma unroll
            for (int nt = 0; nt < 4; nt++) {
                uint32_t bf[2];
                ldmat_x2(bf, aBf + ((nt * 8 * SPAD + ks * 16) << 1));
                mma16816(acc[nt], af, bf);
            }
        }
    }

    const int r = m0 + wid * 16 + (lane >> 2);
    const int c = (lane & 3) * 2;
#pragma unroll
    for (int nt = 0; nt < 4; nt++) {
        int col = c + nt * 8;
        float b0 = sCb[col], b1 = sCb[col + 1];
        *(float2*)&g_fproj[(size_t)r * 32 + col] =
            make_float2(acc[nt][0] + b0, acc[nt][1] + b1);
        *(float2*)&g_fproj[(size_t)(r + 8) * 32 + col] =
            make_float2(acc[nt][2] + b0, acc[nt][3] + b1);
    }
}

// ------------------------------- bones -------------------------------------
// Warp-per-batch: 8 batches per 256-thread block; weights loaded once; the
// 3-iteration loop uses ONLY __syncwarp.  g2 is register-blocked: lane owns
// columns (lane, lane+32) across all 16 bones -> 576 LDS instead of 2048.
#define BONES_SMEM ((2436 + 8 * 2272) * 4)
__global__ void __launch_bounds__(256)
bones_kernel(const float* __restrict__ poses2d, const float* __restrict__ conf,
             const float* __restrict__ cW1, const float* __restrict__ cW2,
             const float* __restrict__ cb2, const float* __restrict__ cW3,
             const float* __restrict__ cb3, const float* __restrict__ db3,
             float* __restrict__ out)
{
    extern __shared__ float bs[];
    float* w1  = bs;            // [4][32]
    float* w2  = bs + 128;      // [32][64]
    float* b2  = bs + 2176;     // [64]
    float* w3s = bs + 2240;     // [64][3]
    float* b3  = bs + 2432;     // [3]

    const int tid = threadIdx.x;
    const int u = tid >> 5, lane = tid & 31;

    if (tid < 128) w1[tid] = cW1[tid];
    for (int idx = tid; idx < 2048; idx += 256) w2[idx] = cW2[idx];
    if (tid < 64)  b2[tid] = cb2[tid];
    if (tid < 192) w3s[tid] = cW3[tid];
    if (tid < 3)   b3[tid] = cb3[tid];
    __syncthreads();            // only block barrier

    float* pw    = bs + 2436 + u * 2272;
    float* p3    = pw;          // [75]
    float* cf    = pw + 76;     // [25]
    float* basef = pw + 104;    // [16][32]
    float* g1    = pw + 616;    // [16][32]
    float* g2    = pw + 1128;   // [16][64]
    float* dir4  = pw + 2152;   // [16][4]
    float* bfm   = pw + 2216;   // [16][3]
    float* upd   = pw + 2264;   // [3]

    const int batch = blockIdx.x * 8 + u;
    const size_t rowbase = (size_t)batch * 25;
    const size_t fbase   = (size_t)batch * 17;

    const float db3v = db3[0];
    if (lane < 25) cf[lane] = conf[rowbase + lane];
    for (int idx = lane; idx < 75; idx += 32) {
        int j = idx / 3, c = idx - j * 3;
        p3[idx] = (c < 2) ? poses2d[(rowbase + j) * 2 + c]
                          : (g_depth[rowbase + j] + db3v);
    }
    for (int idx = lane; idx < 512; idx += 32) {
        int bone = idx >> 5, n = idx & 31;
        float fp = g_fproj[(fbase + c_par[bone]) * 32 + n];
        float fc = g_fproj[(fbase + c_chi[bone]) * 32 + n];
        basef[idx] = 0.5f * (fp + fc);
    }
    __syncwarp();

    const float bv0 = b2[lane], bv1 = b2[32 + lane];

    for (int it = 0; it < 3; it++) {
        if (lane < 16) {
            int p = c_par[lane], c = c_chi[lane];
            float vx = p3[c * 3 + 0] - p3[p * 3 + 0];
            float vy = p3[c * 3 + 1] - p3[p * 3 + 1];
            float vz = p3[c * 3 + 2] - p3[p * 3 + 2];
            float len = sqrtf(vx * vx + vy * vy + vz * vz);
            float inv = 1.f / (len + 1e-8f);
            dir4[lane * 4 + 0] = vx * inv;
            dir4[lane * 4 + 1] = vy * inv;
            dir4[lane * 4 + 2] = vz * inv;
            dir4[lane * 4 + 3] = len;
        }
        __syncwarp();
        for (int idx = lane; idx < 512; idx += 32) {
            int bone = idx >> 5, n = idx & 31;
            float v = basef[idx]
                    + dir4[bone * 4 + 0] * w1[n]       + dir4[bone * 4 + 1] * w1[32 + n]
                    + dir4[bone * 4 + 2] * w1[64 + n]  + dir4[bone * 4 + 3] * w1[96 + n];
            g1[idx] = fmaxf(v, 0.f);
        }
        __syncwarp();
        // g2: lane owns columns (lane, lane+32) for all 16 bones.
        {
            float a0[16], a1[16];
#pragma unroll
            for (int bone = 0; bone < 16; bone++) { a0[bone] = bv0; a1[bone] = bv1; }
#pragma unroll 4
            for (int i = 0; i < 32; i++) {
                float w0  = w2[i * 64 + lane];
                float w1v = w2[i * 64 + 32 + lane];
#pragma unroll
                for (int bone = 0; bone < 16; bone++) {
                    float g = g1[bone * 32 + i];
                    a0[bone] += g * w0;
                    a1[bone] += g * w1v;
                }
            }
#pragma unroll
            for (int bone = 0; bone < 16; bone++) {
                g2[bone * 64 + lane]      = fmaxf(a0[bone], 0.f);
                g2[bone * 64 + 32 + lane] = fmaxf(a1[bone], 0.f);
            }
        }
        __syncwarp();
        for (int idx = lane; idx < 48; idx += 32) {
            int bone = idx / 3, c = idx - bone * 3;
            float s = b3[c];
            const float* g2b = g2 + bone * 64;
#pragma unroll
            for (int i = 0; i < 64; i++) s += g2b[i] * w3s[i * 3 + c];
            bfm[idx] = s;
        }
        __syncwarp();
        if (lane < 3) {
            float s = 0.f;
#pragma unroll
            for (int bone = 0; bone < 16; bone++) s += bfm[bone * 3 + lane];
            upd[lane] = 0.1f * (s * (1.f / 16.f));
        }
        __syncwarp();
        for (int idx = lane; idx < 75; idx += 32) {
            int j = idx / 3, c = idx - j * 3;
            p3[idx] = (p3[idx] + upd[c]) * cf[j];
        }
        __syncwarp();
    }

    for (int idx = lane; idx < 75; idx += 32) out[rowbase * 3 + idx] = p3[idx];
}

// ------------------------------ launcher -----------------------------------
extern "C" void kernel_launch(void* const* d_in, const int* in_sizes, int n_in,
                              void* d_out, int out_size) {
    (void)in_sizes; (void)n_in; (void)out_size;
    const float* poses2d  = (const float*)d_in[0];
    const float* features = (const float*)d_in[1];
    const float* conf     = (const float*)d_in[2];
    const float* dW1 = (const float*)d_in[3];
    const float* db1 = (const float*)d_in[4];
    const float* dW2 = (const float*)d_in[5];
    const float* db2 = (const float*)d_in[6];
    const float* dW3 = (const float*)d_in[7];
    const float* db3 = (const float*)d_in[8];
    const float* cW1 = (const float*)d_in[9];
    const float* cb1 = (const float*)d_in[10];
    const float* cW2 = (const float*)d_in[11];
    const float* cb2 = (const float*)d_in[12];
    const float* cW3 = (const float*)d_in[13];
    const float* cb3 = (const float*)d_in[14];
    float* out = (float*)d_out;

    __nv_bfloat16 *pFbf, *pBT1, *pBTf, *pBT2, *pH1;
    cudaGetSymbolAddress((void**)&pFbf, g_Fbf);
    cudaGetSymbolAddress((void**)&pBT1, g_BT1);
    cudaGetSymbolAddress((void**)&pBTf, g_BTf);
    cudaGetSymbolAddress((void**)&pBT2, g_BT2);
    cudaGetSymbolAddress((void**)&pH1, g_H1);

    cudaFuncSetAttribute(gemm_db<0>, cudaFuncAttributeMaxDynamicSharedMemorySize, GEMM_SMEM);
    cudaFuncSetAttribute(gemm_db<1>, cudaFuncAttributeMaxDynamicSharedMemorySize, GEMM_SMEM);
    cudaFuncSetAttribute(bones_kernel, cudaFuncAttributeMaxDynamicSharedMemorySize, BONES_SMEM);

    // side stream + fork/join events (host-side creation is capture-safe;
    // graph replay carries only the recorded dependencies)
    cudaStream_t s2;
    cudaStreamCreateWithFlags(&s2, cudaStreamNonBlocking);
    cudaEvent_t evPrep, evFproj;
    cudaEventCreateWithFlags(&evPrep, cudaEventDisableTiming);
    cudaEventCreateWithFlags(&evFproj, cudaEventDisableTiming);

    // 1) convert features + transpose weights + zero depth
    prep_kernel<<<8192, 256>>>(features, dW1, dW2, cW1);
    cudaEventRecord(evPrep, 0);

    // fork: fproj runs concurrently with the GEMMs (depends only on prep)
    cudaStreamWaitEvent(s2, evPrep, 0);
    fproj_kernel<<<FROWS / 128, 256, 0, s2>>>(pFbf, pBTf, cb1);
    cudaEventRecord(evFproj, s2);

    // 2) GEMM1: H1 = relu(Fbf @ dW1 + db1)  (bf16 out, N=1024)
    gemm_db<0><<<dim3(8, MROWS / 128), 256, GEMM_SMEM>>>(
        pFbf, K1, pBT1, K1, db1, pH1, 1024, K1, nullptr);

    // 3) GEMM2 fused GEMV: depth += relu(H1@dW2+db2) @ dW3
    gemm_db<1><<<dim3(4, MROWS / 128), 256, GEMM_SMEM>>>(
        pH1, K2, pBT2, K2, db2, nullptr, 0, K2, dW3);

    // join: bones needs depth (GEMM2) and fproj
    cudaStreamWaitEvent(0, evFproj, 0);

    // 4) skeletal refinement (adds db3 to depth), warp-per-batch
    bones_kernel<<<1024, 256, BONES_SMEM>>>(
        poses2d, conf, cW1, cW2, cb2, cW3, cb3, db3, out);

    cudaStreamDestroy(s2);
    cudaEventDestroy(evPrep);
    cudaEventDestroy(evFproj);
}